// round 17
// baseline (speedup 1.0000x reference)
#include <cuda_runtime.h>
#include <cuda.h>
#include <cuda_fp16.h>
#include <math.h>
#include <cstdint>

// ---------------- problem constants ----------------
#define M_TOK   16384
#define DIMX    1024
#define HID     2048
#define NEXP    8
#define TOPK    2
#define RROWS   (M_TOK * TOPK)

#define WSCALE   1024.0f
#define IWSCALE  (1.0f / 1024.0f)

// ---------------- device scratch ----------------
__device__ __align__(1024) __half g_xn[(size_t)M_TOK * DIMX];
__device__ __align__(1024) __half g_h[(size_t)(RROWS + 128) * HID];
__device__ __align__(1024) __half g_down[(size_t)RROWS * DIMX];
__device__ __align__(1024) __half g_wup[(size_t)NEXP * 2 * HID * DIMX];
__device__ __align__(1024) __half g_wdn[(size_t)NEXP * DIMX * HID];
__device__ int    g_cnt[NEXP];
__device__ int    g_list[NEXP * M_TOK];
__device__ int    g_se[RROWS];
__device__ int    g_sj[RROWS];
__device__ float  g_sw[RROWS];

// ---------------- helpers ----------------
__device__ __forceinline__ unsigned sptr(const void* p) {
    return (unsigned)__cvta_generic_to_shared(p);
}
__device__ __forceinline__ void cp16(unsigned s, const void* g) {
    asm volatile("cp.async.cg.shared.global [%0], [%1], 16;" :: "r"(s), "l"(g));
}
__device__ __forceinline__ void cp_arrive(uint32_t mbar) {  // .noinc load-bearing (round 12)
    asm volatile("cp.async.mbarrier.arrive.noinc.shared::cta.b64 [%0];" :: "r"(mbar) : "memory");
}
__device__ __forceinline__ void mbar_init(uint32_t a, uint32_t cnt) {
    asm volatile("mbarrier.init.shared.b64 [%0], %1;" :: "r"(a), "r"(cnt) : "memory");
}
__device__ __forceinline__ void mbar_arrive(uint32_t a) {
    asm volatile("mbarrier.arrive.shared.b64 _, [%0];" :: "r"(a) : "memory");
}
__device__ __forceinline__ void expect_tx(uint32_t a, uint32_t bytes) {
    asm volatile("mbarrier.arrive.expect_tx.shared.b64 _, [%0], %1;" :: "r"(a), "r"(bytes) : "memory");
}
__device__ __forceinline__ void tma2d(uint32_t smem, const CUtensorMap* m, int x, int y, uint32_t mbar) {
    asm volatile(
        "cp.async.bulk.tensor.2d.shared::cta.global.tile.mbarrier::complete_tx::bytes "
        "[%0], [%1, {%2, %3}], [%4];"
        :: "r"(smem), "l"(m), "r"(x), "r"(y), "r"(mbar) : "memory");
}
__device__ __forceinline__ void mbar_wait(uint32_t a, uint32_t par) {
    uint32_t done;
    asm volatile(
        "{\n\t.reg .pred p;\n\t"
        "mbarrier.try_wait.parity.acquire.cta.shared::cta.b64 p, [%1], %2;\n\t"
        "selp.b32 %0, 1, 0, p;\n\t}"
        : "=r"(done) : "r"(a), "r"(par) : "memory");
    if (!done) {
        asm volatile(
            "{\n\t.reg .pred P1;\n\t"
            "WL%=:\n\t"
            "mbarrier.try_wait.parity.acquire.cta.shared::cta.b64 P1, [%0], %1, 0x989680;\n\t"
            "@P1 bra.uni WD%=;\n\t"
            "bra.uni WL%=;\n\t"
            "WD%=:\n\t}"
            :: "r"(a), "r"(par) : "memory");
    }
}

__device__ __forceinline__ void mma_f16(float* c, const uint32_t* a, uint32_t b0, uint32_t b1) {
    asm volatile(
        "mma.sync.aligned.m16n8k16.row.col.f32.f16.f16.f32 "
        "{%0,%1,%2,%3}, {%4,%5,%6,%7}, {%8,%9}, {%0,%1,%2,%3};"
        : "+f"(c[0]), "+f"(c[1]), "+f"(c[2]), "+f"(c[3])
        : "r"(a[0]), "r"(a[1]), "r"(a[2]), "r"(a[3]), "r"(b0), "r"(b1));
}
__device__ __forceinline__ void ldsm_x4(uint32_t* r, uint32_t addr) {
    asm volatile("ldmatrix.sync.aligned.m8n8.x4.shared.b16 {%0,%1,%2,%3}, [%4];"
        : "=r"(r[0]), "=r"(r[1]), "=r"(r[2]), "=r"(r[3]) : "r"(addr));
}
__device__ __forceinline__ void ldsm_x2(uint32_t& r0, uint32_t& r1, uint32_t addr) {
    asm volatile("ldmatrix.sync.aligned.m8n8.x2.shared.b16 {%0,%1}, [%2];"
        : "=r"(r0), "=r"(r1) : "r"(addr));
}

// ---------------- GEMM geometry: BK=64, 3 stages, 128x128 block, 8 warps 2Mx4N ----------------
#define BK      64
#define BM      128
#define BN      128
#define STAGES  3
// k_up: A padded rows (gather via cp.async), B SW128 128B rows (TMA)
#define UP_ASTRH 72
#define UP_ABYT  (BM * UP_ASTRH * 2)      // 18432
#define UP_BBYT  16384                     // 128 rows x 128B
#define UP_STG   (UP_ABYT + UP_BBYT)       // 34816
#define UP_BAR   (STAGES * UP_STG)         // 104448
#define UP_TOKS  (UP_BAR + 64)
#define UP_SMEM  (UP_TOKS + 512)           // 105024
// k_down: A and B both SW128 128B rows (TMA)
#define DN_ABYT  16384
#define DN_BBYT  16384
#define DN_STG   (DN_ABYT + DN_BBYT)       // 32768
#define DN_BAR   (STAGES * DN_STG)         // 98304
#define DN_SMEM  (DN_BAR + 64)             // 98368

// ---------------- kernel 1: convert weights to fp16*1024 (+ zero counters) ----------------
__global__ void k_prep(const float* __restrict__ wu, const float* __restrict__ wd) {
    if (blockIdx.x == 0 && threadIdx.x < NEXP) g_cnt[threadIdx.x] = 0;
    int i = blockIdx.x * blockDim.x + threadIdx.x;
    int stride = gridDim.x * blockDim.x;
    const int NU = NEXP * 2 * HID * DIMX / 4;
    const int ND = NEXP * DIMX * HID / 4;
    const float4* u4 = (const float4*)wu;
    const float4* d4 = (const float4*)wd;
    for (int j = i; j < NU; j += stride) {
        float4 v = u4[j];
        __half2* o = (__half2*)(g_wup + (size_t)j * 4);
        o[0] = __floats2half2_rn(v.x * WSCALE, v.y * WSCALE);
        o[1] = __floats2half2_rn(v.z * WSCALE, v.w * WSCALE);
    }
    for (int j = i; j < ND; j += stride) {
        float4 v = d4[j];
        __half2* o = (__half2*)(g_wdn + (size_t)j * 4);
        o[0] = __floats2half2_rn(v.x * WSCALE, v.y * WSCALE);
        o[1] = __floats2half2_rn(v.z * WSCALE, v.w * WSCALE);
    }
}

// ---------------- kernel 2: RMSNorm + router + top2 + softmax + list build ----------------
__global__ void k_rms_router(const float* __restrict__ x,
                             const float* __restrict__ scale,
                             const float* __restrict__ wr) {
    __shared__ float sx[DIMX];
    __shared__ float sred[8];
    __shared__ float sscore[8];
    int t = blockIdx.x, tid = threadIdx.x;

    const float4* xr = (const float4*)(x + (size_t)t * DIMX);
    float4 v = xr[tid];
    float ss = v.x * v.x + v.y * v.y + v.z * v.z + v.w * v.w;
    #pragma unroll
    for (int o = 16; o; o >>= 1) ss += __shfl_xor_sync(0xffffffffu, ss, o);
    if ((tid & 31) == 0) sred[tid >> 5] = ss;
    __syncthreads();
    if (tid == 0) {
        float a = 0.f;
        #pragma unroll
        for (int i = 0; i < 8; i++) a += sred[i];
        sred[0] = a;
    }
    __syncthreads();
    float ms = sred[0] * (1.0f / (float)DIMX);
    float rs = rsqrtf(ms + 1e-6f);
    float4 sc = ((const float4*)scale)[tid];
    float4 xn;
    xn.x = v.x * sc.x * rs; xn.y = v.y * sc.y * rs;
    xn.z = v.z * sc.z * rs; xn.w = v.w * sc.w * rs;
    ((float4*)sx)[tid] = xn;
    __half2* hp = (__half2*)(g_xn + (size_t)t * DIMX + 4 * tid);
    hp[0] = __floats2half2_rn(xn.x, xn.y);
    hp[1] = __floats2half2_rn(xn.z, xn.w);
    __syncthreads();

    int w = tid >> 5, lane = tid & 31;
    const float* wrow = wr + w * DIMX;
    float acc = 0.f;
    #pragma unroll 8
    for (int j = lane; j < DIMX; j += 32) acc += sx[j] * __ldg(wrow + j);
    #pragma unroll
    for (int o = 16; o; o >>= 1) acc += __shfl_xor_sync(0xffffffffu, acc, o);
    if (lane == 0) sscore[w] = acc;
    __syncthreads();

    if (tid == 0) {
        float s0 = -1e30f; int i0 = 0;
        #pragma unroll
        for (int i = 0; i < 8; i++) { float s = sscore[i]; if (s > s0) { s0 = s; i0 = i; } }
        float s1 = -1e30f; int i1 = 0;
        #pragma unroll
        for (int i = 0; i < 8; i++) { if (i == i0) continue; float s = sscore[i]; if (s > s1) { s1 = s; i1 = i; } }
        float e1 = __expf(s1 - s0);
        float w0 = 1.f / (1.f + e1);
        float w1 = e1 * w0;
        int p0 = atomicAdd(&g_cnt[i0], 1);
        g_list[i0 * M_TOK + p0] = t;
        g_se[2 * t] = i0; g_sj[2 * t] = p0; g_sw[2 * t] = w0;
        int p1 = atomicAdd(&g_cnt[i1], 1);
        g_list[i1 * M_TOK + p1] = t;
        g_se[2 * t + 1] = i1; g_sj[2 * t + 1] = p1; g_sw[2 * t + 1] = w1;
    }
}

// ---------------- scheduling: blockIdx.y -> (expert, row-tile) ----------------
struct Sched { int e, rt, valid, pbase; bool ok; };
__device__ __forceinline__ Sched sched_rowtile(int tile) {
    Sched s; s.ok = false;
    int off = 0;
    for (int e = 0; e < NEXP; e++) {
        int c = g_cnt[e];
        int nt = (c + 127) >> 7;
        if (tile < nt) {
            s.e = e; s.rt = tile;
            s.valid = min(128, c - tile * 128);
            s.pbase = off + tile * 128;
            s.ok = true;
            return s;
        }
        tile -= nt; off += c;
    }
    return s;
}

// ---------------- kernel 3: up GEMM; A cp.async gather, B TMA ----------------
#define KTU (DIMX / BK)   // 16

__global__ void __launch_bounds__(256, 2) k_up(const __grid_constant__ CUtensorMap tmB) {
    extern __shared__ __half smem[];
    uint32_t sb = sptr(smem);
    int tid = threadIdx.x, wid = tid >> 5, lane = tid & 31;
    int g = lane >> 2, tg = lane & 3;

    Sched sc = sched_rowtile(blockIdx.y);
    if (!sc.ok) return;
    int c0 = blockIdx.x * 64;
    int lbase = sc.e * M_TOK + sc.rt * 128;
    int eb = sc.e * 2 * HID;

    uint32_t fullb = sb + UP_BAR;
    uint32_t emptyb = sb + UP_BAR + 32;
    if (tid == 0) {
        #pragma unroll
        for (int s = 0; s < STAGES; s++) {
            mbar_init(fullb + 8 * s, 257);   // 256 cp_arrive + 1 expect_tx
            mbar_init(emptyb + 8 * s, 8);
        }
    }
    int* toks = (int*)((char*)smem + UP_TOKS);
    if (tid < 128)
        toks[tid] = (tid < sc.valid) ? g_list[lbase + tid] : g_list[lbase];
    __syncthreads();

    // A loader (gather): thread t -> row t>>1, 32-half group t&1 (4 cp16); padded rows
    int arow = tid >> 1;
    const __half* a_src = g_xn + (size_t)toks[arow] * DIMX + (tid & 1) * 32;
    uint32_t a_dst = sb + (arow * UP_ASTRH + (tid & 1) * 32) * 2;

    auto produce = [&](int ti, int st) {
        uint32_t so = (uint32_t)st * UP_STG;
        const __half* ap = a_src + ti * BK;
        cp16(a_dst + so,      ap);
        cp16(a_dst + so + 16, ap + 8);
        cp16(a_dst + so + 32, ap + 16);
        cp16(a_dst + so + 48, ap + 24);
        cp_arrive(fullb + 8 * st);
        if (tid == 0) {
            uint32_t bdst = sb + so + UP_ABYT;
            expect_tx(fullb + 8 * st, 16384);
            tma2d(bdst,        &tmB, ti * BK, eb + c0,       fullb + 8 * st);        // u rows -> 0..63
            tma2d(bdst + 8192, &tmB, ti * BK, eb + HID + c0, fullb + 8 * st);        // gate -> 64..127
        }
    };

    produce(0, 0);
    produce(1, 1);

    float acc[4][4][4] = {};
    int wm = (wid >> 2) * 64, wq = wid & 3;
    uint32_t a_off = ((wm + (lane & 15)) * UP_ASTRH + (lane >> 4) * 8) * 2;
    int bl = lane & 7, kh = (lane >> 3) & 1;

    for (int kt = 0; kt < KTU; kt++) {
        int s = kt % 3;
        mbar_wait(fullb + 8 * s, (kt / 3) & 1);
        uint32_t SbA = sb + (uint32_t)s * UP_STG;
        uint32_t SbB = SbA + UP_ABYT;
        #pragma unroll
        for (int ks = 0; ks < 4; ks++) {
            uint32_t a[4][4];
            #pragma unroll
            for (int mt = 0; mt < 4; mt++)
                ldsm_x4(a[mt], SbA + a_off + mt * (16 * UP_ASTRH * 2) + ks * 32);
            #pragma unroll
            for (int nt = 0; nt < 4; nt++) {
                int rn = ((nt < 2) ? (wq * 16 + nt * 8) : (64 + wq * 16 + (nt - 2) * 8)) + bl;
                uint32_t c = (uint32_t)((ks * 2 + kh) ^ (rn & 7));
                uint32_t b0, b1;
                ldsm_x2(b0, b1, SbB + rn * 128 + (c << 4));
                #pragma unroll
                for (int mt = 0; mt < 4; mt++)
                    mma_f16(acc[mt][nt], a[mt], b0, b1);
            }
        }
        if (lane == 0) mbar_arrive(emptyb + 8 * s);
        int ti = kt + 2;
        if (ti < KTU) {
            int s2 = ti % 3;
            if (ti >= 3) mbar_wait(emptyb + 8 * s2, ((ti / 3) - 1) & 1);
            produce(ti, s2);
        }
    }

    // SwiGLU: warp covers HID cols [c0+wq*16, +16); nt 0..1 = u, nt 2..3 = gate (same cols)
    int ch0 = c0 + wq * 16;
    #pragma unroll
    for (int mt = 0; mt < 4; mt++) {
        #pragma unroll
        for (int hf = 0; hf < 2; hf++) {
            int r = wm + mt * 16 + g + hf * 8;
            if (r < sc.valid) {
                __half* orow = g_h + (size_t)(sc.pbase + r) * HID;
                #pragma unroll
                for (int nt = 0; nt < 2; nt++) {
                    int ch = ch0 + nt * 8 + 2 * tg;
                    float u0 = acc[mt][nt][hf * 2]     * IWSCALE;
                    float u1 = acc[mt][nt][hf * 2 + 1] * IWSCALE;
                    float q0 = acc[mt][nt + 2][hf * 2]     * IWSCALE;
                    float q1 = acc[mt][nt + 2][hf * 2 + 1] * IWSCALE;
                    float h0 = u0 * (q0 / (1.f + __expf(-q0)));
                    float h1 = u1 * (q1 / (1.f + __expf(-q1)));
                    *(__half2*)(orow + ch) = __floats2half2_rn(h0, h1);
                }
            }
        }
    }
}

// ---------------- kernel 4: down GEMM; A and B via TMA ----------------
#define KTD (HID / BK)    // 32

__global__ void __launch_bounds__(256, 2) k_down(const __grid_constant__ CUtensorMap tmA,
                                                 const __grid_constant__ CUtensorMap tmB) {
    extern __shared__ __half smem[];
    uint32_t sb = sptr(smem);
    int tid = threadIdx.x, wid = tid >> 5, lane = tid & 31;
    int g = lane >> 2, tg = lane & 3;

    Sched sc = sched_rowtile(blockIdx.y);
    if (!sc.ok) return;
    int n0 = blockIdx.x * BN;
    int brow0 = sc.e * DIMX + n0;

    uint32_t fullb = sb + DN_BAR;
    uint32_t emptyb = sb + DN_BAR + 32;
    if (tid == 0) {
        #pragma unroll
        for (int s = 0; s < STAGES; s++) {
            mbar_init(fullb + 8 * s, 1);   // single expect_tx arrival
            mbar_init(emptyb + 8 * s, 8);
        }
    }
    __syncthreads();

    auto produce = [&](int ti, int st) {
        if (tid == 0) {
            uint32_t so = sb + (uint32_t)st * DN_STG;
            expect_tx(fullb + 8 * st, 32768);
            tma2d(so,            &tmA, ti * BK, sc.pbase, fullb + 8 * st);
            tma2d(so + DN_ABYT,  &tmB, ti * BK, brow0,    fullb + 8 * st);
        }
    };

    produce(0, 0);
    produce(1, 1);

    float acc[4][4][4] = {};
    int wm = (wid >> 2) * 64, wq = wid & 3;
    int bl = lane & 7, kh = (lane >> 3) & 1;
    int ra = wm + (lane & 15);
    int kha = lane >> 4;

    for (int kt = 0; kt < KTD; kt++) {
        int s = kt % 3;
        mbar_wait(fullb + 8 * s, (kt / 3) & 1);
        uint32_t SbA = sb + (uint32_t)s * DN_STG;
        uint32_t SbB = SbA + DN_ABYT;
        #pragma unroll
        for (int ks = 0; ks < 4; ks++) {
            uint32_t a[4][4];
            #pragma unroll
            for (int mt = 0; mt < 4; mt++) {
                int rm = ra + mt * 16;
                uint32_t c = (uint32_t)((ks * 2 + kha) ^ (rm & 7));
                ldsm_x4(a[mt], SbA + rm * 128 + (c << 4));
            }
            #pragma unroll
            for (int nt = 0; nt < 4; nt++) {
                int rn = wq * 32 + nt * 8 + bl;
                uint32_t c = (uint32_t)((ks * 2 + kh) ^ (rn & 7));
                uint32_t b0, b1;
                ldsm_x2(b0, b1, SbB + rn * 128 + (c << 4));
                #pragma unroll
                for (int mt = 0; mt < 4; mt++)
                    mma_f16(acc[mt][nt], a[mt], b0, b1);
            }
        }
        if (lane == 0) mbar_arrive(emptyb + 8 * s);
        int ti = kt + 2;
        if (ti < KTD) {
            int s2 = ti % 3;
            if (ti >= 3) mbar_wait(emptyb + 8 * s2, ((ti / 3) - 1) & 1);
            produce(ti, s2);
        }
    }

    #pragma unroll
    for (int mt = 0; mt < 4; mt++) {
        #pragma unroll
        for (int hf = 0; hf < 2; hf++) {
            int r = wm + mt * 16 + g + hf * 8;
            if (r < sc.valid) {
                __half* orow = g_down + (size_t)(sc.pbase + r) * DIMX + n0;
                #pragma unroll
                for (int nt = 0; nt < 4; nt++) {
                    int cc = wq * 32 + nt * 8 + 2 * tg;
                    float vx = acc[mt][nt][hf * 2]     * IWSCALE;
                    float vy = acc[mt][nt][hf * 2 + 1] * IWSCALE;
                    *(__half2*)(orow + cc) = __floats2half2_rn(vx, vy);
                }
            }
        }
    }
}

// ---------------- kernel 5: combine ----------------
__global__ void k_combine(const float* __restrict__ x, float* __restrict__ out) {
    int t = blockIdx.x, tid = threadIdx.x;
    int e0 = g_se[2 * t], j0 = g_sj[2 * t];
    int e1 = g_se[2 * t + 1], j1 = g_sj[2 * t + 1];
    float w0 = g_sw[2 * t], w1 = g_sw[2 * t + 1];
    int off0 = 0, off1 = 0;
    #pragma unroll
    for (int i = 0; i < 8; i++) {
        int ci = __ldg(&g_cnt[i]);
        if (i < e0) off0 += ci;
        if (i < e1) off1 += ci;
    }
    int p0 = off0 + j0, p1 = off1 + j1;
    const float4* x4 = (const float4*)(x + (size_t)t * DIMX);
    const __half2* d0 = (const __half2*)(g_down + (size_t)p0 * DIMX) + 2 * tid;
    const __half2* d1 = (const __half2*)(g_down + (size_t)p1 * DIMX) + 2 * tid;
    float4 a = x4[tid];
    float2 u0 = __half22float2(d0[0]), u1 = __half22float2(d0[1]);
    float2 v0 = __half22float2(d1[0]), v1 = __half22float2(d1[1]);
    float4 o;
    o.x = a.x + w0 * u0.x + w1 * v0.x;
    o.y = a.y + w0 * u0.y + w1 * v0.y;
    o.z = a.z + w0 * u1.x + w1 * v1.x;
    o.w = a.w + w0 * u1.y + w1 * v1.y;
    ((float4*)(out + (size_t)t * DIMX))[tid] = o;
}

// ---------------- host: tensor map plumbing ----------------
typedef CUresult (*PFN_encodeTiled)(
    CUtensorMap*, CUtensorMapDataType, cuuint32_t, void*,
    const cuuint64_t*, const cuuint64_t*, const cuuint32_t*, const cuuint32_t*,
    CUtensorMapInterleave, CUtensorMapSwizzle, CUtensorMapL2promotion, CUtensorMapFloatOOBfill);

static void encode2d(PFN_encodeTiled enc, CUtensorMap* m, void* base,
                     uint64_t inner, uint64_t outer, uint32_t bi, uint32_t bo) {
    cuuint64_t dims[2] = {inner, outer};
    cuuint64_t strides[1] = {inner * 2};          // bytes per row (fp16)
    cuuint32_t box[2] = {bi, bo};
    cuuint32_t estr[2] = {1, 1};
    enc(m, CU_TENSOR_MAP_DATA_TYPE_UINT16, 2, base, dims, strides, box, estr,
        CU_TENSOR_MAP_INTERLEAVE_NONE, CU_TENSOR_MAP_SWIZZLE_128B,
        CU_TENSOR_MAP_L2_PROMOTION_L2_128B, CU_TENSOR_MAP_FLOAT_OOB_FILL_NONE);
}

extern "C" void kernel_launch(void* const* d_in, const int* in_sizes, int n_in,
                              void* d_out, int out_size) {
    const float* x     = (const float*)d_in[0];
    const float* scale = (const float*)d_in[1];
    const float* wr    = (const float*)d_in[2];
    const float* wu    = (const float*)d_in[3];
    const float* wd    = (const float*)d_in[4];
    float* out = (float*)d_out;

    void* fn = nullptr;
    cudaDriverEntryPointQueryResult qr;
    cudaGetDriverEntryPoint("cuTensorMapEncodeTiled", &fn, cudaEnableDefault, &qr);
    PFN_encodeTiled enc = (PFN_encodeTiled)fn;

    void *pwup, *pwdn, *ph;
    cudaGetSymbolAddress(&pwup, g_wup);
    cudaGetSymbolAddress(&pwdn, g_wdn);
    cudaGetSymbolAddress(&ph,   g_h);

    CUtensorMap mUpB, mDnA, mDnB;
    encode2d(enc, &mUpB, pwup, DIMX, (uint64_t)NEXP * 2 * HID, 64, 64);
    encode2d(enc, &mDnA, ph,   HID,  (uint64_t)RROWS + 128,    64, 128);
    encode2d(enc, &mDnB, pwdn, HID,  (uint64_t)NEXP * DIMX,    64, 128);

    cudaFuncSetAttribute(k_up,   cudaFuncAttributeMaxDynamicSharedMemorySize, UP_SMEM);
    cudaFuncSetAttribute(k_down, cudaFuncAttributeMaxDynamicSharedMemorySize, DN_SMEM);

    k_prep<<<2048, 256>>>(wu, wd);
    k_rms_router<<<M_TOK, 256>>>(x, scale, wr);
    k_up  <<<dim3(HID / 64, 264), 256, UP_SMEM>>>(mUpB);         // (32, 264)
    k_down<<<dim3(DIMX / BN, 264), 256, DN_SMEM>>>(mDnA, mDnB);  // (8, 264)
    k_combine<<<M_TOK, 256>>>(x, out);
}